// round 3
// baseline (speedup 1.0000x reference)
#include <cuda_runtime.h>
#include <math.h>

#define FD      128
#define KTAPS   15
#define FS      160
#define OV      40
#define NFR     500
#define BATCH   32
#define NSAMP   (NFR * FS)          // 80000
#define WIN_C   (FS + KTAPS - 1)    // 174
#define WIN_P   (OV + KTAPS - 1)    // 54
#define LGL     1.1512925464970229f // 10*C
#define GAIN_A  0.6907755278982137f // 6*C   (GAIN_B == 0)
#define PSTRIDE 20                  // 15 kern + gain + ggain, padded
#define NHEAD   17                  // 15 taps + fg + gg
#define FPB     8                   // frames per block in K1 (one warp each)

// per-frame parameter scratch: [B][NFR][PSTRIDE]
__device__ float g_params[BATCH * NFR * PSTRIDE];

// ---------------------------------------------------------------------------
// K1: warp-per-frame. 17 dots -> normalized comb kernel + gains -> scratch.
// Weights staged to smem once per block (8 frames share them).
// ---------------------------------------------------------------------------
__global__ __launch_bounds__(256, 8)
void comb1d_params_kernel(const float* __restrict__ features,
                          const float* __restrict__ ck_w,
                          const float* __restrict__ ck_b,
                          const float* __restrict__ fg_w,
                          const float* __restrict__ fg_b,
                          const float* __restrict__ gg_w,
                          const float* __restrict__ gg_b)
{
    const int b    = blockIdx.y;
    const int tid  = threadIdx.x;
    const int lane = tid & 31;
    const int wid  = tid >> 5;

    __shared__ float wsm[NHEAD][FD];  // 8704 B
    __shared__ float bsm[NHEAD];

    // stage weights + biases (rows 0-14: ck_w, 15: fg_w, 16: gg_w)
    for (int i = tid; i < NHEAD * FD; i += 256) {
        const int j = i >> 7;
        const int d = i & 127;
        wsm[j][d] = (j < KTAPS) ? ck_w[i] : ((j == KTAPS) ? fg_w[d] : gg_w[d]);
    }
    if (tid < NHEAD)
        bsm[tid] = (tid < KTAPS) ? ck_b[tid] : ((tid == KTAPS) ? fg_b[0] : gg_b[0]);
    __syncthreads();

    const int f = blockIdx.x * FPB + wid;
    if (f >= NFR) return;

    const float* Fc = features + ((size_t)b * NFR + f) * FD;
    const float x0 = Fc[lane];
    const float x1 = Fc[lane + 32];
    const float x2 = Fc[lane + 64];
    const float x3 = Fc[lane + 96];

    // 17 dots; after each butterfly-reduce, lane j keeps dot j in v
    float v = 0.0f;
    #pragma unroll
    for (int j = 0; j < NHEAD; j++) {
        float s = fmaf(x0, wsm[j][lane],
                  fmaf(x1, wsm[j][lane + 32],
                  fmaf(x2, wsm[j][lane + 64],
                       x3 * wsm[j][lane + 96])));
        #pragma unroll
        for (int o = 16; o; o >>= 1) s += __shfl_xor_sync(0xffffffffu, s, o);
        if (lane == j) v = s + bsm[j];
    }

    // L2 norm over taps 0..14 (warp-local)
    float sq = (lane < KTAPS) ? v * v : 0.0f;
    #pragma unroll
    for (int o = 16; o; o >>= 1) sq += __shfl_xor_sync(0xffffffffu, sq, o);
    const float inv = 1.0f / (1e-6f + sqrtf(sq));

    float* P = g_params + ((size_t)b * NFR + f) * PSTRIDE;
    if (lane < KTAPS)        P[lane] = v * inv;
    else if (lane == KTAPS)  P[15]   = expf(-fmaxf(v, 0.0f) + LGL);   // gain
    else if (lane == 16)     P[16]   = expf(GAIN_A * tanhf(v));       // ggain
}

// ---------------------------------------------------------------------------
// K2: 15-tap conv for current frame + prev-frame tail, overlap-add, store
// ---------------------------------------------------------------------------
__global__ __launch_bounds__(256, 8)
void comb1d_conv_kernel(const float* __restrict__ x,
                        const int*   __restrict__ lags,
                        float*       __restrict__ out)
{
    const int f   = blockIdx.x;
    const int b   = blockIdx.y;
    const int tid = threadIdx.x;

    __shared__ float prm_c[NHEAD]; // kern[15], gain, ggain (current frame)
    __shared__ float prm_p[NHEAD]; // same for previous frame
    __shared__ float xx_c[WIN_C];  // current frame conv window (t in [0,174))
    __shared__ float xx_p[WIN_P];  // prev frame window, tail region (t in [160,214))
    __shared__ float tail[OV];

    const float* xb = x + (size_t)b * NSAMP;
    const int fp = (f > 0) ? (f - 1) : 0;

    // ---- per-frame params (current + prev) ----
    if (tid < NHEAD)
        prm_c[tid] = g_params[((size_t)b * NFR + f)  * PSTRIDE + tid];
    else if (tid < 2 * NHEAD)
        prm_p[tid - NHEAD] = g_params[((size_t)b * NFR + fp) * PSTRIDE + (tid - NHEAD)];

    // ---- stage x windows (raw index = t + f*FS - lag - 7; zero outside [0,NSAMP)) ----
    const int lag_c   = lags[b * NFR + f];
    const int lag_p   = lags[b * NFR + fp];
    const int start_c = f * FS - lag_c - 7;   // current window t = 0
    const int start_p = f * FS - lag_p - 7;   // prev-frame window at its t = 160
    if (tid < WIN_C) {
        int g = start_c + tid;
        xx_c[tid] = (g >= 0 && g < NSAMP) ? xb[g] : 0.0f;
    } else if (tid < WIN_C + WIN_P) {
        int i = tid - WIN_C;
        int g = start_p + i;
        xx_p[i] = (g >= 0 && g < NSAMP) ? xb[g] : 0.0f;
    }
    __syncthreads();

    // ---- conv + gain: threads [0,160) -> current samples, [160,200) -> prev tail ----
    float val = 0.0f;
    if (tid < FS) {
        float s = 0.0f;
        #pragma unroll
        for (int k = 0; k < KTAPS; k++) s = fmaf(xx_c[tid + k], prm_c[k], s);
        float pt = xb[f * FS + tid];
        val = prm_c[16] * fmaf(s, prm_c[15], pt);
    } else if (tid < FS + OV) {
        const int j = tid - FS;
        float s = 0.0f;
        #pragma unroll
        for (int k = 0; k < KTAPS; k++) s = fmaf(xx_p[j + k], prm_p[k], s);
        float pt = xb[f * FS + j];                 // == x[(f-1)*FS + 160 + j]
        float tv = prm_p[16] * fmaf(s, prm_p[15], pt);
        tail[j] = (f > 0) ? tv : 0.0f;
    }
    __syncthreads();

    // ---- overlap-add head (win1[j] == 1 - win2[j]) and store ----
    if (tid < FS) {
        float o = val;
        if (tid < OV) {
            float w2 = 0.5f + 0.5f * cosf((tid + 0.5f) * (float)(M_PI / OV));
            o = val * (1.0f - w2) + tail[tid] * w2;
        }
        out[(size_t)b * NSAMP + f * FS + tid] = o;
    }
}

extern "C" void kernel_launch(void* const* d_in, const int* in_sizes, int n_in,
                              void* d_out, int out_size)
{
    const float* x        = (const float*)d_in[0];
    const float* features = (const float*)d_in[1];
    const int*   lags     = (const int*)  d_in[2];
    const float* ck_w     = (const float*)d_in[3];
    const float* ck_b     = (const float*)d_in[4];
    const float* fg_w     = (const float*)d_in[5];
    const float* fg_b     = (const float*)d_in[6];
    const float* gg_w     = (const float*)d_in[7];
    const float* gg_b     = (const float*)d_in[8];
    float* out = (float*)d_out;

    dim3 grid1((NFR + FPB - 1) / FPB, BATCH);
    comb1d_params_kernel<<<grid1, 256>>>(features, ck_w, ck_b, fg_w, fg_b, gg_w, gg_b);

    dim3 grid2(NFR, BATCH);
    comb1d_conv_kernel<<<grid2, 256>>>(x, lags, out);
}

// round 17
// speedup vs baseline: 1.3630x; 1.3630x over previous
#include <cuda_runtime.h>
#include <math.h>

#define FD      128
#define KTAPS   15
#define FS      160
#define OV      40
#define NFR     500
#define BATCH   32
#define NSAMP   (NFR * FS)          // 80000
#define WIN_C   (FS + KTAPS - 1)    // 174
#define WIN_P   (OV + KTAPS - 1)    // 54
#define LGL     1.1512925464970229f // 10*C
#define GAIN_A  0.6907755278982137f // 6*C   (GAIN_B == 0)
#define PSTRIDE 20                  // 15 kern + gain + ggain, padded
#define NHEAD   17                  // 15 taps + fg + gg
#define FPB     8                   // frames per block (one warp each in K2)
#define FPB1    16                  // frames per block in K1 (two per warp)

// per-frame parameter scratch: [B][NFR][PSTRIDE]
__device__ float g_params[BATCH * NFR * PSTRIDE];

// ---------------------------------------------------------------------------
// K1: two frames per warp. 17 dots each -> normalized comb kernel + gains.
// Weights staged to smem once per block; each smem weight read feeds 2 frames.
// ---------------------------------------------------------------------------
__global__ __launch_bounds__(256, 8)
void comb1d_params_kernel(const float* __restrict__ features,
                          const float* __restrict__ ck_w,
                          const float* __restrict__ ck_b,
                          const float* __restrict__ fg_w,
                          const float* __restrict__ fg_b,
                          const float* __restrict__ gg_w,
                          const float* __restrict__ gg_b)
{
    const int b    = blockIdx.y;
    const int tid  = threadIdx.x;
    const int lane = tid & 31;
    const int wid  = tid >> 5;

    __shared__ float wsm[NHEAD][FD];  // 8704 B
    __shared__ float bsm[NHEAD];

    // stage weights + biases (rows 0-14: ck_w, 15: fg_w, 16: gg_w)
    for (int i = tid; i < NHEAD * FD; i += 256) {
        const int j = i >> 7;
        const int d = i & 127;
        wsm[j][d] = (j < KTAPS) ? ck_w[i] : ((j == KTAPS) ? fg_w[d] : gg_w[d]);
    }
    if (tid < NHEAD)
        bsm[tid] = (tid < KTAPS) ? ck_b[tid] : ((tid == KTAPS) ? fg_b[0] : gg_b[0]);
    __syncthreads();

    const int f0 = blockIdx.x * FPB1 + wid * 2;   // this warp's first frame
    if (f0 >= NFR) return;
    const bool has2 = (f0 + 1 < NFR);
    const int  f1   = has2 ? (f0 + 1) : f0;       // clamp (results discarded)

    const float* Fa = features + ((size_t)b * NFR + f0) * FD;
    const float* Fb = features + ((size_t)b * NFR + f1) * FD;
    const float a0 = Fa[lane], a1 = Fa[lane + 32], a2 = Fa[lane + 64], a3 = Fa[lane + 96];
    const float b0 = Fb[lane], b1 = Fb[lane + 32], b2 = Fb[lane + 64], b3 = Fb[lane + 96];

    // 17 dots for each frame; after reduce, lane j keeps dot j
    float va = 0.0f, vb = 0.0f;
    #pragma unroll
    for (int j = 0; j < NHEAD; j++) {
        const float w0 = wsm[j][lane];
        const float w1 = wsm[j][lane + 32];
        const float w2 = wsm[j][lane + 64];
        const float w3 = wsm[j][lane + 96];
        float sa = fmaf(a0, w0, fmaf(a1, w1, fmaf(a2, w2, a3 * w3)));
        float sb = fmaf(b0, w0, fmaf(b1, w1, fmaf(b2, w2, b3 * w3)));
        #pragma unroll
        for (int o = 16; o; o >>= 1) {
            sa += __shfl_xor_sync(0xffffffffu, sa, o);
            sb += __shfl_xor_sync(0xffffffffu, sb, o);
        }
        if (lane == j) { va = sa + bsm[j]; vb = sb + bsm[j]; }
    }

    // L2 norm over taps 0..14 (warp-local), both frames
    float qa = (lane < KTAPS) ? va * va : 0.0f;
    float qb = (lane < KTAPS) ? vb * vb : 0.0f;
    #pragma unroll
    for (int o = 16; o; o >>= 1) {
        qa += __shfl_xor_sync(0xffffffffu, qa, o);
        qb += __shfl_xor_sync(0xffffffffu, qb, o);
    }
    const float inva = 1.0f / (1e-6f + sqrtf(qa));
    const float invb = 1.0f / (1e-6f + sqrtf(qb));

    float* Pa = g_params + ((size_t)b * NFR + f0) * PSTRIDE;
    if (lane < KTAPS)        Pa[lane] = va * inva;
    else if (lane == KTAPS)  Pa[15]   = expf(-fmaxf(va, 0.0f) + LGL);
    else if (lane == 16)     Pa[16]   = expf(GAIN_A * tanhf(va));

    if (has2) {
        float* Pb = g_params + ((size_t)b * NFR + f1) * PSTRIDE;
        if (lane < KTAPS)        Pb[lane] = vb * invb;
        else if (lane == KTAPS)  Pb[15]   = expf(-fmaxf(vb, 0.0f) + LGL);
        else if (lane == 16)     Pb[16]   = expf(GAIN_A * tanhf(vb));
    }
}

// ---------------------------------------------------------------------------
// K2: warp-per-frame. Stage windows, prev-frame tail conv, current conv,
// overlap-add, store. No block-level barriers.
// ---------------------------------------------------------------------------
__global__ __launch_bounds__(256)
void comb1d_conv_kernel(const float* __restrict__ x,
                        const int*   __restrict__ lags,
                        float*       __restrict__ out)
{
    const int tid  = threadIdx.x;
    const int lane = tid & 31;
    const int w    = tid >> 5;
    const int f    = blockIdx.x * FPB + w;
    const int b    = blockIdx.y;

    __shared__ float sm[FPB][WIN_C + WIN_P + OV];   // 268 floats/warp

    if (f >= NFR) return;   // warp-uniform exit; only __syncwarp below

    float* xx_c = sm[w];                    // current window, t in [0,174)
    float* xx_p = sm[w] + WIN_C;            // prev window tail region
    float* tail = sm[w] + WIN_C + WIN_P;    // prev-frame tail samples

    const float* xb = x + (size_t)b * NSAMP;
    const int fp = (f > 0) ? (f - 1) : 0;
    const int lag_c = lags[b * NFR + f];
    const int lag_p = lags[b * NFR + fp];
    const int start_c = f * FS - lag_c - 7;   // raw x idx of window t = 0
    const int start_p = f * FS - lag_p - 7;   // prev-frame window at its t = 160

    // hoisted hann weights for this lane's two head samples (si = lane, 32+lane)
    const float w2_0 = 0.5f + 0.5f * __cosf((lane + 0.5f)  * (float)(M_PI / OV));
    const float w2_1 = 0.5f + 0.5f * __cosf((lane + 32.5f) * (float)(M_PI / OV));

    // ---- stage both windows (228 floats, 8 rounds/lane) ----
    #pragma unroll
    for (int i = lane; i < WIN_C + WIN_P; i += 32) {
        const int g = (i < WIN_C) ? (start_c + i) : (start_p + (i - WIN_C));
        sm[w][i] = (g >= 0 && g < NSAMP) ? xb[g] : 0.0f;
    }
    __syncwarp();

    const float* Pc = g_params + ((size_t)b * NFR + f)  * PSTRIDE;
    const float* Pp = g_params + ((size_t)b * NFR + fp) * PSTRIDE;

    // ---- prev-frame tail (40 samples), taps in registers ----
    {
        float kp[KTAPS];
        #pragma unroll
        for (int k = 0; k < KTAPS; k++) kp[k] = Pp[k];
        const float gain_p = Pp[15];
        const float gg_p   = Pp[16];
        #pragma unroll
        for (int it = 0; it < 2; it++) {
            const int j = it * 32 + lane;
            if (j < OV) {
                float s = 0.0f;
                #pragma unroll
                for (int k = 0; k < KTAPS; k++) s = fmaf(xx_p[j + k], kp[k], s);
                const float pt = xb[f * FS + j];   // == x[(f-1)*FS + 160 + j]
                tail[j] = (f > 0) ? gg_p * fmaf(s, gain_p, pt) : 0.0f;
            }
        }
    }
    __syncwarp();

    // ---- current frame: 160 samples, overlap-add head, store ----
    {
        float kc[KTAPS];
        #pragma unroll
        for (int k = 0; k < KTAPS; k++) kc[k] = Pc[k];
        const float gain_c = Pc[15];
        const float gg_c   = Pc[16];
        float* ob = out + (size_t)b * NSAMP + f * FS;
        #pragma unroll
        for (int i = 0; i < FS / 32; i++) {
            const int si = i * 32 + lane;
            float s = 0.0f;
            #pragma unroll
            for (int k = 0; k < KTAPS; k++) s = fmaf(xx_c[si + k], kc[k], s);
            const float pt = xb[f * FS + si];
            float val = gg_c * fmaf(s, gain_c, pt);
            if (i == 0) {
                val = val * (1.0f - w2_0) + tail[si] * w2_0;
            } else if (i == 1 && si < OV) {
                val = val * (1.0f - w2_1) + tail[si] * w2_1;
            }
            ob[si] = val;
        }
    }
}

extern "C" void kernel_launch(void* const* d_in, const int* in_sizes, int n_in,
                              void* d_out, int out_size)
{
    const float* x        = (const float*)d_in[0];
    const float* features = (const float*)d_in[1];
    const int*   lags     = (const int*)  d_in[2];
    const float* ck_w     = (const float*)d_in[3];
    const float* ck_b     = (const float*)d_in[4];
    const float* fg_w     = (const float*)d_in[5];
    const float* fg_b     = (const float*)d_in[6];
    const float* gg_w     = (const float*)d_in[7];
    const float* gg_b     = (const float*)d_in[8];
    float* out = (float*)d_out;

    dim3 grid1((NFR + FPB1 - 1) / FPB1, BATCH);
    comb1d_params_kernel<<<grid1, 256>>>(features, ck_w, ck_b, fg_w, fg_b, gg_w, gg_b);

    dim3 grid2((NFR + FPB - 1) / FPB, BATCH);
    comb1d_conv_kernel<<<grid2, 256>>>(x, lags, out);
}